// round 1
// baseline (speedup 1.0000x reference)
#include <cuda_runtime.h>

// Problem constants
#define G_   8
#define FG_  16
#define J_   8
#define W_   31
#define PAD1_ 15
#define L_   262144
#define TL_  512          // k positions per CTA
#define KT_  4            // k positions per thread
#define NTHREADS_ 256

// fma.rn.f32x2: packed 2xf32 FMA (full-rate FFMA2 on sm_103a; plain FFMA is half rate)
__device__ __forceinline__ unsigned long long ffma2(unsigned long long a,
                                                    unsigned long long b,
                                                    unsigned long long c) {
    unsigned long long d;
    asm("fma.rn.f32x2 %0, %1, %2, %3;" : "=l"(d) : "l"(a), "l"(b), "l"(c));
    return d;
}

__device__ __forceinline__ unsigned long long dup2(float x) {
    unsigned long long d;
    asm("mov.b64 %0, {%1, %1};" : "=l"(d) : "f"(x));
    return d;
}

__device__ __forceinline__ void unpack2(unsigned long long v, float& lo, float& hi) {
    asm("mov.b64 {%0, %1}, %2;" : "=f"(lo), "=f"(hi) : "l"(v));
}

// Main kernel: interior correlation y[g,f,k] = sum_{j,w} x[rel[g,j], k-15+w] * K[g,f,j,w]
// Each CTA: one group g, TL_=512 consecutive k, all 16 filters.
// Thread: fb = filter-block (8 filters as 4 f32x2 pairs), 4 consecutive k.
__global__ void __launch_bounds__(NTHREADS_)
conv_main(const float* __restrict__ x,
          const float* __restrict__ params,
          const int* __restrict__ rel,
          float* __restrict__ out)
{
    __shared__ float ws[J_ * W_ * FG_];   // [j][w][f] — filter pairs contiguous

    const int g    = blockIdx.y;
    const int tile = blockIdx.x;
    const int tid  = threadIdx.x;

    // Transpose this group's weights [f][j][w] -> [j][w][f] into SMEM
    const float* pg = params + g * (FG_ * J_ * W_);
    for (int idx = tid; idx < FG_ * J_ * W_; idx += NTHREADS_) {
        int f = idx / (J_ * W_);
        int r = idx - f * (J_ * W_);
        int j = r / W_;
        int w = r - j * W_;
        ws[(j * W_ + w) * FG_ + f] = pg[idx];
    }
    __syncthreads();

    const int fb   = tid >> 7;          // 0..1 : filters [fb*8, fb*8+8)
    const int kidx = tid & 127;
    const int kb   = tile * TL_ + kidx * KT_;

    unsigned long long acc[4][KT_];
#pragma unroll
    for (int p = 0; p < 4; ++p)
#pragma unroll
        for (int t = 0; t < KT_; ++t) acc[p][t] = 0ull;

    // window covers x[kb-16 .. kb+19] (36 floats, 16B-aligned base)
    const bool safe = (kb >= 16) && (kb + 20 <= L_);

    for (int j = 0; j < J_; ++j) {
        const int row = __ldg(rel + g * J_ + j);
        const float* xr = x + row * L_;

        float xw[36];
        if (safe) {
            const float4* xp = (const float4*)(xr + kb - 16);
#pragma unroll
            for (int q = 0; q < 9; ++q) {
                float4 v = __ldg(xp + q);
                xw[4 * q + 0] = v.x; xw[4 * q + 1] = v.y;
                xw[4 * q + 2] = v.z; xw[4 * q + 3] = v.w;
            }
        } else {
            // clamped loads: pollutes only boundary outputs, which conv_edges overwrites
#pragma unroll
            for (int i = 0; i < 36; ++i) {
                int ix = kb - 16 + i;
                ix = max(0, min(L_ - 1, ix));
                xw[i] = __ldg(xr + ix);
            }
        }

        const float* wsj = ws + j * (W_ * FG_) + fb * 8;
#pragma unroll
        for (int w = 0; w < W_; ++w) {
            // 4 filter-pairs for this (j,w): one LDS.64 each, warp-uniform broadcast
            const unsigned long long* wq =
                (const unsigned long long*)(wsj + w * FG_);
            unsigned long long w0 = wq[0];
            unsigned long long w1 = wq[1];
            unsigned long long w2 = wq[2];
            unsigned long long w3 = wq[3];
#pragma unroll
            for (int t = 0; t < KT_; ++t) {
                unsigned long long xd = dup2(xw[w + t + 1]);
                acc[0][t] = ffma2(xd, w0, acc[0][t]);
                acc[1][t] = ffma2(xd, w1, acc[1][t]);
                acc[2][t] = ffma2(xd, w2, acc[2][t]);
                acc[3][t] = ffma2(xd, w3, acc[3][t]);
            }
        }
    }

    // Write: per filter, 4 consecutive k -> one float4 store
#pragma unroll
    for (int p = 0; p < 4; ++p) {
        float a0[KT_], a1[KT_];
#pragma unroll
        for (int t = 0; t < KT_; ++t) unpack2(acc[p][t], a0[t], a1[t]);
        const int f0 = fb * 8 + 2 * p;
        float4* o0 = (float4*)(out + (g * FG_ + f0) * L_ + kb);
        float4* o1 = (float4*)(out + (g * FG_ + f0 + 1) * L_ + kb);
        *o0 = make_float4(a0[0], a0[1], a0[2], a0[3]);
        *o1 = make_float4(a1[0], a1[1], a1[2], a1[3]);
    }
}

// Boundary kernel: the reference anchors the kernel at the array ends and
// truncates (NOT zero padding).
//  left  k in [0,15):       y[k] = sum_j sum_{w=0}^{k+15}  x[row, w]      * K[j,w]
//  right k = L-15+i, i<15:  y[k] = sum_j sum_{w=i+1}^{30}  x[row, L-31+w] * K[j,w]
__global__ void conv_edges(const float* __restrict__ x,
                           const float* __restrict__ params,
                           const int* __restrict__ rel,
                           float* __restrict__ out)
{
    const int gf = blockIdx.x;          // 0..127
    const int g = gf >> 4;
    const int f = gf & 15;
    const int lane = threadIdx.x;
    const float* pk = params + (g * FG_ + f) * (J_ * W_);   // [j][w]

    if (lane < PAD1_) {
        const int k = lane;
        float s = 0.f;
        for (int j = 0; j < J_; ++j) {
            const int row = __ldg(rel + g * J_ + j);
            const float* xr = x + row * L_;
            for (int w = 0; w <= k + PAD1_; ++w)
                s += xr[w] * pk[j * W_ + w];
        }
        out[(g * FG_ + f) * L_ + k] = s;
    } else if (lane >= 16 && lane < 31) {
        const int i = lane - 16;              // 0..14
        const int k = L_ - PAD1_ + i;         // L-15 .. L-1
        float s = 0.f;
        for (int j = 0; j < J_; ++j) {
            const int row = __ldg(rel + g * J_ + j);
            const float* xr = x + row * L_;
            for (int w = i + 1; w < W_; ++w)
                s += xr[L_ - W_ + w] * pk[j * W_ + w];
        }
        out[(g * FG_ + f) * L_ + k] = s;
    }
}

extern "C" void kernel_launch(void* const* d_in, const int* in_sizes, int n_in,
                              void* d_out, int out_size)
{
    const float* x      = (const float*)d_in[0];
    const float* params = (const float*)d_in[1];
    const int*   rel    = (const int*)d_in[2];
    float* out = (float*)d_out;

    dim3 grid(L_ / TL_, G_);          // 512 x 8 = 4096 CTAs
    conv_main<<<grid, NTHREADS_>>>(x, params, rel, out);
    conv_edges<<<G_ * FG_, 32>>>(x, params, rel, out);
}